// round 9
// baseline (speedup 1.0000x reference)
#include <cuda_runtime.h>

#define B_ROWS   16384
#define NFEAT    1024
#define FACTORS  64
#define TOTAL    524288
#define STRIDE   128            // max row count ~57 (binomial, 17-sigma safe)

// ---------------------------------------------------------------------------
// Scratch (device globals; BSS-zeroed at load, self-cleaned every launch)
// ---------------------------------------------------------------------------
__device__ int  g_counts[B_ROWS];
__device__ int2 g_pairs[B_ROWS * STRIDE];     // (feat id, K[u,n] bits) per item

// G table (256 KB) is hot -> pin in L1.
__device__ __forceinline__ float2 ldg_el2(const float* p) {
    float2 v;
    asm("ld.global.nc.L1::evict_last.v2.f32 {%0,%1}, [%2];"
        : "=f"(v.x), "=f"(v.y) : "l"(p));
    return v;
}

// ---------------------------------------------------------------------------
// 1) scatter: gathers K[u,n] here (latency hides in 131K-thread kernel) and
//    buckets (n, kv) pairs by batch row. Also zeroes the output accumulator.
// ---------------------------------------------------------------------------
__global__ __launch_bounds__(256) void scatter_kernel(
    const int*   __restrict__ sample_idx,
    const int*   __restrict__ feat_idx,
    const int*   __restrict__ user,
    const float* __restrict__ K,
    float*       __restrict__ out)
{
    if (blockIdx.x == 0 && threadIdx.x == 0) out[0] = 0.0f;

    const int base = (blockIdx.x * 256 + threadIdx.x) * 4;
    const int4 s = __ldg((const int4*)(sample_idx + base));
    const int4 f = __ldg((const int4*)(feat_idx + base));

    // user rows (64KB table -> L1/L2 hits)
    const int u0 = __ldg(user + s.x);
    const int u1 = __ldg(user + s.y);
    const int u2 = __ldg(user + s.z);
    const int u3 = __ldg(user + s.w);

    // random K gathers (DRAM sectors) - 4 independent chains
    const float k0 = __ldg(K + (u0 << 10) + f.x);
    const float k1 = __ldg(K + (u1 << 10) + f.y);
    const float k2 = __ldg(K + (u2 << 10) + f.z);
    const float k3 = __ldg(K + (u3 << 10) + f.w);

    const int p0 = atomicAdd(&g_counts[s.x], 1);
    const int p1 = atomicAdd(&g_counts[s.y], 1);
    const int p2 = atomicAdd(&g_counts[s.z], 1);
    const int p3 = atomicAdd(&g_counts[s.w], 1);

    if (p0 < STRIDE) g_pairs[s.x * STRIDE + p0] = make_int2(f.x, __float_as_int(k0));
    if (p1 < STRIDE) g_pairs[s.y * STRIDE + p1] = make_int2(f.y, __float_as_int(k1));
    if (p2 < STRIDE) g_pairs[s.z * STRIDE + p2] = make_int2(f.z, __float_as_int(k2));
    if (p3 < STRIDE) g_pairs[s.w * STRIDE + p3] = make_int2(f.w, __float_as_int(k3));
}

// ---------------------------------------------------------------------------
// 2) compute: one warp per batch row b.  NO shuffles in the inner loop:
//    each item is a uniform broadcast pair-load + one G row load + 2 FMA,
//    fully independent across iterations -> compiler can pipeline deeply.
//    w_b = sum kv * G[n] (2 floats/lane); result += H[u] . w_b (ONE H dot/b)
// ---------------------------------------------------------------------------
__global__ __launch_bounds__(256) void compute_kernel(
    const int*   __restrict__ user,
    const float* __restrict__ H,
    const float* __restrict__ G,
    float*       __restrict__ out)
{
    const int lane = threadIdx.x & 31;
    const int wid  = threadIdx.x >> 5;
    const int b    = blockIdx.x * 8 + wid;        // 2048 x 8 = 16384 rows

    const int u   = __ldg(user + b);
    const int cnt = min(g_counts[b], STRIDE);
    if (lane == 0) g_counts[b] = 0;               // self-clean for next replay

    const int2* __restrict__ row = g_pairs + b * STRIDE;
    const float* Gl = G + 2 * lane;

    float wx = 0.0f, wy = 0.0f;                   // w[2*lane], w[2*lane+1]

    #pragma unroll 8
    for (int j = 0; j < cnt; ++j) {
        const int2  p  = __ldg(row + j);          // uniform broadcast, 1 wf
        const float kv = __int_as_float(p.y);
        const float2 g = ldg_el2(Gl + (p.x << 6));
        wx = fmaf(kv, g.x, wx);
        wy = fmaf(kv, g.y, wy);
    }

    // one H-row load + dot per b
    const float2 h = *(const float2*)(H + (u << 6) + 2 * lane);
    float r = fmaf(wx, h.x, wy * h.y);

    #pragma unroll
    for (int off = 16; off > 0; off >>= 1)
        r += __shfl_xor_sync(0xFFFFFFFFu, r, off);

    __shared__ float warp_sums[8];
    if (lane == 0) warp_sums[wid] = r;
    __syncthreads();
    if (wid == 0) {
        float v = (lane < 8) ? warp_sums[lane] : 0.0f;
        #pragma unroll
        for (int off = 4; off > 0; off >>= 1)
            v += __shfl_xor_sync(0xFFFFFFFFu, v, off);
        if (lane == 0) atomicAdd(out, v);
    }
}

// ---------------------------------------------------------------------------
extern "C" void kernel_launch(void* const* d_in, const int* in_sizes, int n_in,
                              void* d_out, int out_size)
{
    const int*   user       = (const int*)  d_in[0];
    const int*   sample_idx = (const int*)  d_in[1];
    const int*   feat_idx   = (const int*)  d_in[2];
    const float* H          = (const float*)d_in[3];
    const float* G          = (const float*)d_in[4];
    const float* K          = (const float*)d_in[5];
    float*       out        = (float*)d_out;

    (void)in_sizes; (void)n_in; (void)out_size;

    scatter_kernel<<<TOTAL / 4 / 256, 256>>>(sample_idx, feat_idx, user, K, out);
    compute_kernel<<<B_ROWS / 8, 256>>>(user, H, G, out);
}

// round 10
// speedup vs baseline: 1.0282x; 1.0282x over previous
#include <cuda_runtime.h>

#define B_ROWS   16384
#define NFEAT    1024
#define FACTORS  64
#define TOTAL    524288
#define STRIDE   128            // max row count ~57 (binomial, 17-sigma safe)

// ---------------------------------------------------------------------------
// Scratch (device globals; BSS-zeroed at load, self-cleaned every launch)
// ---------------------------------------------------------------------------
__device__ int  g_counts[B_ROWS];
__device__ int2 g_pairs[B_ROWS * STRIDE];     // (feat id, K[u,n] bits) per item

// G table (256 KB) is hot -> pin in L1.
__device__ __forceinline__ float2 ldg_el2(const float* p) {
    float2 v;
    asm("ld.global.nc.L1::evict_last.v2.f32 {%0,%1}, [%2];"
        : "=f"(v.x), "=f"(v.y) : "l"(p));
    return v;
}

// ---------------------------------------------------------------------------
// 1) scatter: gathers K[u,n] (8 independent chains/thread) and buckets
//    (n, kv) pairs by batch row. Also zeroes the output accumulator.
// ---------------------------------------------------------------------------
__global__ __launch_bounds__(256) void scatter_kernel(
    const int*   __restrict__ sample_idx,
    const int*   __restrict__ feat_idx,
    const int*   __restrict__ user,
    const float* __restrict__ K,
    float*       __restrict__ out)
{
    if (blockIdx.x == 0 && threadIdx.x == 0) out[0] = 0.0f;

    const int base = (blockIdx.x * 256 + threadIdx.x) * 8;

    int s[8], f[8];
    *(int4*)(s)     = __ldg((const int4*)(sample_idx + base));
    *(int4*)(s + 4) = __ldg((const int4*)(sample_idx + base + 4));
    *(int4*)(f)     = __ldg((const int4*)(feat_idx + base));
    *(int4*)(f + 4) = __ldg((const int4*)(feat_idx + base + 4));

    int uu[8];
    #pragma unroll
    for (int i = 0; i < 8; ++i) uu[i] = __ldg(user + s[i]);

    float kv[8];
    #pragma unroll
    for (int i = 0; i < 8; ++i) kv[i] = __ldg(K + (uu[i] << 10) + f[i]);

    int p[8];
    #pragma unroll
    for (int i = 0; i < 8; ++i) p[i] = atomicAdd(&g_counts[s[i]], 1);

    #pragma unroll
    for (int i = 0; i < 8; ++i)
        if (p[i] < STRIDE)
            g_pairs[s[i] * STRIDE + p[i]] = make_int2(f[i], __float_as_int(kv[i]));
}

// ---------------------------------------------------------------------------
// 2) compute: TWO warps per batch row (even/odd items), manual depth-4
//    register prefetch of pairs so the L2 pair latency never sits on the
//    critical chain. No shuffles in the inner loop.
//    w_b = sum kv * G[n] (2 floats/lane); result += H[u] . w_b
// ---------------------------------------------------------------------------
__global__ __launch_bounds__(256, 3) void compute_kernel(
    const int*   __restrict__ user,
    const float* __restrict__ H,
    const float* __restrict__ G,
    float*       __restrict__ out)
{
    const int lane = threadIdx.x & 31;
    const int wid  = threadIdx.x >> 5;
    const int w    = blockIdx.x * 8 + wid;        // 4096 x 8 = 32768 warps
    const int b    = w >> 1;                      // 2 warps per row
    const int half = w & 1;                       // even/odd items

    const int u   = __ldg(user + b);
    const int cnt = min(g_counts[b], STRIDE);
    __syncthreads();                              // all reads of g_counts done
    if (half == 0 && lane == 0) g_counts[b] = 0;  // self-clean for next replay

    const int2* __restrict__ row = g_pairs + b * STRIDE;
    const float* Gl = G + 2 * lane;

    float wx = 0.0f, wy = 0.0f;                   // w[2*lane], w[2*lane+1]

    // depth-4 prefetch of this warp's stride-2 item stream
    int2 P[4];
    #pragma unroll
    for (int k = 0; k < 4; ++k) {
        const int jj = half + 2 * k;
        P[k] = (jj < cnt) ? __ldg(row + jj) : make_int2(0, 0);
    }

    for (int j = half; j < cnt; j += 8) {
        #pragma unroll
        for (int k = 0; k < 4; ++k) {
            const int2 p = P[k];
            const int jn = j + 8 + 2 * k;
            P[k] = (jn < cnt) ? __ldg(row + jn) : make_int2(0, 0);
            const float kv = __int_as_float(p.y);   // 0 past cnt -> no-op
            const float2 g = ldg_el2(Gl + (p.x << 6));
            wx = fmaf(kv, g.x, wx);
            wy = fmaf(kv, g.y, wy);
        }
    }

    // H dot on this warp's partial w (sum over both halves is linear)
    const float2 h = *(const float2*)(H + (u << 6) + 2 * lane);
    float r = fmaf(wx, h.x, wy * h.y);

    #pragma unroll
    for (int off = 16; off > 0; off >>= 1)
        r += __shfl_xor_sync(0xFFFFFFFFu, r, off);

    __shared__ float warp_sums[8];
    if (lane == 0) warp_sums[wid] = r;
    __syncthreads();
    if (wid == 0) {
        float v = (lane < 8) ? warp_sums[lane] : 0.0f;
        #pragma unroll
        for (int off = 4; off > 0; off >>= 1)
            v += __shfl_xor_sync(0xFFFFFFFFu, v, off);
        if (lane == 0) atomicAdd(out, v);
    }
}

// ---------------------------------------------------------------------------
extern "C" void kernel_launch(void* const* d_in, const int* in_sizes, int n_in,
                              void* d_out, int out_size)
{
    const int*   user       = (const int*)  d_in[0];
    const int*   sample_idx = (const int*)  d_in[1];
    const int*   feat_idx   = (const int*)  d_in[2];
    const float* H          = (const float*)d_in[3];
    const float* G          = (const float*)d_in[4];
    const float* K          = (const float*)d_in[5];
    float*       out        = (float*)d_out;

    (void)in_sizes; (void)n_in; (void)out_size;

    scatter_kernel<<<TOTAL / 8 / 256, 256>>>(sample_idx, feat_idx, user, K, out);
    compute_kernel<<<B_ROWS * 2 / 8, 256>>>(user, H, G, out);
}

// round 12
// speedup vs baseline: 1.6098x; 1.5657x over previous
#include <cuda_runtime.h>

#define B_ROWS   16384
#define NFEAT    1024
#define FACTORS  64
#define TOTAL    524288

// G table (256 KB) is reused ~512x per row -> pin in L1 (evict_last).
// H rows have little per-SM reuse -> evict_first.
__device__ __forceinline__ float2 ldg_el2(const float* p) {
    float2 v;
    asm("ld.global.nc.L1::evict_last.v2.f32 {%0,%1}, [%2];"
        : "=f"(v.x), "=f"(v.y) : "l"(p));
    return v;
}
__device__ __forceinline__ float2 ldg_ef2(const float* p) {
    float2 v;
    asm("ld.global.nc.L1::evict_first.v2.f32 {%0,%1}, [%2];"
        : "=f"(v.x), "=f"(v.y) : "l"(p));
    return v;
}

__global__ void init_out_kernel(float* out) {
    if (threadIdx.x == 0) out[0] = 0.0f;
}

__global__ __launch_bounds__(256) void kgflex_flat_kernel(
    const int*   __restrict__ user,
    const int*   __restrict__ sample_idx,
    const int*   __restrict__ feat_idx,
    const float* __restrict__ H,
    const float* __restrict__ G,
    const float* __restrict__ K,
    float*       __restrict__ out)
{
    const int lane = threadIdx.x & 31;
    const int wid  = threadIdx.x >> 5;
    const int t    = blockIdx.x * 256 + threadIdx.x;   // exact cover

    // --- per-lane preload of this warp's 32 items (coalesced / gathered once)
    const int b  = __ldg(sample_idx + t);
    const int n  = __ldg(feat_idx + t);
    const int u  = __ldg(user + b);
    const int un = (u << 10) | n;                      // u*1024 + n (27 bits)
    const float kv = __ldg(K + un);

    // --- stage (un, kv) pairs in smem: inner loop reads them via uniform
    //     LDS.64 broadcast at immediate offsets (replaces 2 SHFLs per item)
    __shared__ int2 stage[8][32];
    stage[wid][lane] = make_int2(un, __float_as_int(kv));
    __syncwarp();

    const float* Hl = H + 2 * lane;    // lane covers factors 2l, 2l+1
    const float* Gl = G + 2 * lane;

    float acc = 0.0f;

    // --- depth-1 software pipeline: loads of item j+1 issue before FMAs of j
    int2 p = stage[wid][0];
    float2 h = ldg_ef2(Hl + ((p.x >> 4) & ~63));       // (un>>10)*64
    float2 g = ldg_el2(Gl + ((p.x << 6) & 0xFFFF));    // (un&1023)*64
    float kvc = __int_as_float(p.y);

    #pragma unroll
    for (int j = 0; j < 31; ++j) {
        const int2 pn = stage[wid][j + 1];
        const float2 hn = ldg_ef2(Hl + ((pn.x >> 4) & ~63));
        const float2 gn = ldg_el2(Gl + ((pn.x << 6) & 0xFFFF));

        float d = h.x * g.x;
        d = fmaf(h.y, g.y, d);
        acc = fmaf(kvc, d, acc);

        h = hn; g = gn; kvc = __int_as_float(pn.y);
    }
    {   // tail
        float d = h.x * g.x;
        d = fmaf(h.y, g.y, d);
        acc = fmaf(kvc, d, acc);
    }

    // --- reduction
    #pragma unroll
    for (int off = 16; off > 0; off >>= 1)
        acc += __shfl_xor_sync(0xFFFFFFFFu, acc, off);

    __shared__ float warp_sums[8];
    if (lane == 0) warp_sums[wid] = acc;
    __syncthreads();
    if (wid == 0) {
        float v = (lane < 8) ? warp_sums[lane] : 0.0f;
        #pragma unroll
        for (int off = 4; off > 0; off >>= 1)
            v += __shfl_xor_sync(0xFFFFFFFFu, v, off);
        if (lane == 0) atomicAdd(out, v);
    }
}

extern "C" void kernel_launch(void* const* d_in, const int* in_sizes, int n_in,
                              void* d_out, int out_size)
{
    const int*   user       = (const int*)  d_in[0];
    const int*   sample_idx = (const int*)  d_in[1];
    const int*   feat_idx   = (const int*)  d_in[2];
    const float* H          = (const float*)d_in[3];
    const float* G          = (const float*)d_in[4];
    const float* K          = (const float*)d_in[5];
    float*       out        = (float*)d_out;

    (void)in_sizes; (void)n_in; (void)out_size;

    init_out_kernel<<<1, 32>>>(out);
    kgflex_flat_kernel<<<TOTAL / 256, 256>>>(user, sample_idx, feat_idx,
                                             H, G, K, out);
}